// round 6
// baseline (speedup 1.0000x reference)
#include <cuda_runtime.h>
#include <cstdint>

#define GS 96
#define CC 64               // 8*8 elements per block
#define B_DIM 64
#define THREADS 128
#define WARPS 4
#define TT 8                // tile: TT x TT (i,j) pairs per CTA
#define NT (GS / TT)        // 12 tiles per dimension

// out[b][i][j][c][k]: out[...][c][0] = x[b][i][c], out[...][c][1] = x[b][j][c]
// Per (b,i,j): 128 floats, pair-interleaved (xi[0],xj[0],xi[1],xj[1],...)
__global__ __launch_bounds__(THREADS) void gcom_kernel(const float* __restrict__ x,
                                                       float* __restrict__ out) {
    const int blk = blockIdx.x;              // 0 .. 64*144-1
    const int b   = blk / (NT * NT);
    const int rem = blk - b * (NT * NT);
    const int i0  = (rem / NT) * TT;
    const int j0  = (rem - (rem / NT) * NT) * TT;

    // Stage 8 i-rows + 8 j-rows (2 KB each)
    __shared__ float xi_s[TT * CC];
    __shared__ float xj_s[TT * CC];
    {
        const float4* si =
            reinterpret_cast<const float4*>(x + ((size_t)b * GS + i0) * CC);
        const float4* sj =
            reinterpret_cast<const float4*>(x + ((size_t)b * GS + j0) * CC);
        reinterpret_cast<float4*>(xi_s)[threadIdx.x] = __ldg(si + threadIdx.x);
        reinterpret_cast<float4*>(xj_s)[threadIdx.x] = __ldg(sj + threadIdx.x);
    }
    __syncthreads();

    const int quad = threadIdx.x & 31;   // float4 index within a pair-row (32*16B = 512B)
    const int wid  = threadIdx.x >> 5;   // warp id 0..3 -> jj stride

    const float2* __restrict__ xi2 = reinterpret_cast<const float2*>(xi_s);
    const float2* __restrict__ xj2 = reinterpret_cast<const float2*>(xj_s);

    // Each warp owns jj = wid and jj = wid + 4; hoist those xj pairs to regs.
    const float2 xjv0 = xj2[wid * 32 + quad];
    const float2 xjv1 = xj2[(wid + WARPS) * 32 + quad];

    float4* __restrict__ ob =
        reinterpret_cast<float4*>(out) + (((size_t)b * GS + i0) * GS + j0) * 32;

    #pragma unroll
    for (int ii = 0; ii < TT; ii++) {
        const float2 xiv = xi2[ii * 32 + quad];
        float4* __restrict__ op = ob + (size_t)ii * GS * 32;

        float4 v0, v1;
        v0.x = xiv.x; v0.y = xjv0.x; v0.z = xiv.y; v0.w = xjv0.y;
        v1.x = xiv.x; v1.y = xjv1.x; v1.z = xiv.y; v1.w = xjv1.y;
        op[(size_t)wid * 32 + quad]           = v0;   // default policy stores
        op[(size_t)(wid + WARPS) * 32 + quad] = v1;
    }
}

extern "C" void kernel_launch(void* const* d_in, const int* in_sizes, int n_in,
                              void* d_out, int out_size) {
    const float* x = (const float*)d_in[0];
    float* out = (float*)d_out;
    gcom_kernel<<<B_DIM * NT * NT, THREADS>>>(x, out);
}

// round 7
// speedup vs baseline: 1.0569x; 1.0569x over previous
#include <cuda_runtime.h>
#include <cstdint>

#define GS 96
#define CC 64               // 8*8 elements per block
#define B_DIM 64
#define THREADS 128
#define WARPS 4
#define TT 8                // tile: TT x TT (i,j) pairs per CTA
#define NT (GS / TT)        // 12 tiles per dimension

// out[b][i][j][c][k]: out[...][c][0] = x[b][i][c], out[...][c][1] = x[b][j][c]
// Per (b,i,j): 128 floats, pair-interleaved (xi[0],xj[0],xi[1],xj[1],...)
__global__ __launch_bounds__(THREADS) void gcom_kernel(const float* __restrict__ x,
                                                       float* __restrict__ out) {
    const int blk = blockIdx.x;              // 0 .. 64*144-1
    const int b   = blk / (NT * NT);
    const int rem = blk - b * (NT * NT);
    const int i0  = (rem / NT) * TT;
    const int j0  = (rem - (rem / NT) * NT) * TT;

    // Stage 8 i-rows + 8 j-rows (2 KB each)
    __shared__ float xi_s[TT * CC];
    __shared__ float xj_s[TT * CC];
    {
        const float4* si =
            reinterpret_cast<const float4*>(x + ((size_t)b * GS + i0) * CC);
        const float4* sj =
            reinterpret_cast<const float4*>(x + ((size_t)b * GS + j0) * CC);
        reinterpret_cast<float4*>(xi_s)[threadIdx.x] = __ldg(si + threadIdx.x);
        reinterpret_cast<float4*>(xj_s)[threadIdx.x] = __ldg(sj + threadIdx.x);
    }
    __syncthreads();

    const int quad = threadIdx.x & 31;   // float4 index within a pair-row (32*16B = 512B)
    const int wid  = threadIdx.x >> 5;   // warp id 0..3 -> jj stride

    const float2* __restrict__ xi2 = reinterpret_cast<const float2*>(xi_s);
    const float2* __restrict__ xj2 = reinterpret_cast<const float2*>(xj_s);

    // Each warp owns jj = wid and jj = wid + 4; hoist those xj pairs to regs.
    const float2 xjv0 = xj2[wid * 32 + quad];
    const float2 xjv1 = xj2[(wid + WARPS) * 32 + quad];

    float4* __restrict__ ob =
        reinterpret_cast<float4*>(out) + (((size_t)b * GS + i0) * GS + j0) * 32;

    #pragma unroll
    for (int ii = 0; ii < TT; ii++) {
        const float2 xiv = xi2[ii * 32 + quad];
        float4* __restrict__ op = ob + (size_t)ii * GS * 32;

        float4 v0, v1;
        v0.x = xiv.x; v0.y = xjv0.x; v0.z = xiv.y; v0.w = xjv0.y;
        v1.x = xiv.x; v1.y = xjv1.x; v1.z = xiv.y; v1.w = xjv1.y;
        __stcs(op + (size_t)wid * 32 + quad,           v0);  // streaming, evict-first
        __stcs(op + (size_t)(wid + WARPS) * 32 + quad, v1);
    }
}

extern "C" void kernel_launch(void* const* d_in, const int* in_sizes, int n_in,
                              void* d_out, int out_size) {
    const float* x = (const float*)d_in[0];
    float* out = (float*)d_out;
    gcom_kernel<<<B_DIM * NT * NT, THREADS>>>(x, out);
}